// round 3
// baseline (speedup 1.0000x reference)
#include <cuda_runtime.h>

#define N_NODES 100000
#define N_EDGES 3200000
#define N_GRAPHS 64
#define IN_DIM 128
#define HID 64
#define NPART 240
#define SCAN_B 98          // ceil(100000/1024)
#define BN_EPS 1e-5f

typedef unsigned long long u64;

// ---------------- device scratch (static, no allocs) ----------------
__device__ int   g_cnt[N_NODES];
__device__ int   g_off[N_NODES + 1];
__device__ int   g_cur[N_NODES];
__device__ int   g_csr[N_EDGES];
__device__ float g_dinv[N_NODES];
__device__ float g_hs[(size_t)N_NODES * HID];   // h * dinv (GEMM output)
__device__ float g_agg[(size_t)N_NODES * HID];  // aggregated (pre-BN)
__device__ float g_part[NPART * 128];           // BN partials
__device__ float g_bn[128];                     // [scale(64), shift(64)]
__device__ float g_emb[N_GRAPHS * HID];
__device__ int   g_bsum[SCAN_B];
__device__ int   g_tmp[N_NODES];

// ---------------- packed f32x2 helpers ----------------
__device__ __forceinline__ u64 ffma2(u64 a, u64 b, u64 c) {
    u64 d;
    asm("fma.rn.f32x2 %0, %1, %2, %3;" : "=l"(d) : "l"(a), "l"(b), "l"(c));
    return d;
}
__device__ __forceinline__ u64 fadd2(u64 a, u64 b) {
    u64 d;
    asm("add.rn.f32x2 %0, %1, %2;" : "=l"(d) : "l"(a), "l"(b));
    return d;
}
__device__ __forceinline__ u64 dup2(float v) {
    u64 d;
    asm("mov.b64 %0, {%1, %1};" : "=l"(d) : "f"(v));
    return d;
}

// ---------------- CSR build ----------------
__global__ void k_count(const int* __restrict__ col) {
    int e = blockIdx.x * blockDim.x + threadIdx.x;
    if (e < N_EDGES) atomicAdd(&g_cnt[col[e]], 1);
}

__global__ void k_dinv() {
    int i = blockIdx.x * 1024 + threadIdx.x;
    if (i < N_NODES) g_dinv[i] = rsqrtf((float)g_cnt[i] + 1.0f);
}

__global__ void k_scan1() {
    __shared__ int wsum[32];
    int i = blockIdx.x * 1024 + threadIdx.x;
    int lane = threadIdx.x & 31, wid = threadIdx.x >> 5;
    int x = (i < N_NODES) ? g_cnt[i] : 0;
    #pragma unroll
    for (int d = 1; d < 32; d <<= 1) {
        int t = __shfl_up_sync(0xffffffffu, x, d);
        if (lane >= d) x += t;
    }
    if (lane == 31) wsum[wid] = x;
    __syncthreads();
    if (wid == 0) {
        int y = wsum[lane];
        #pragma unroll
        for (int d = 1; d < 32; d <<= 1) {
            int t = __shfl_up_sync(0xffffffffu, y, d);
            if (lane >= d) y += t;
        }
        wsum[lane] = y;
    }
    __syncthreads();
    if (wid > 0) x += wsum[wid - 1];
    if (i < N_NODES) g_tmp[i] = x;
    if (threadIdx.x == 1023) g_bsum[blockIdx.x] = x;
}

__global__ void k_scan2() {
    __shared__ int s[128];
    int v = (threadIdx.x < SCAN_B) ? g_bsum[threadIdx.x] : 0;
    s[threadIdx.x] = v;
    __syncthreads();
    for (int d = 1; d < 128; d <<= 1) {
        int t = (threadIdx.x >= d) ? s[threadIdx.x - d] : 0;
        __syncthreads();
        s[threadIdx.x] += t;
        __syncthreads();
    }
    if (threadIdx.x < SCAN_B) g_bsum[threadIdx.x] = s[threadIdx.x] - v;  // exclusive
}

__global__ void k_scan3() {
    int i = blockIdx.x * 1024 + threadIdx.x;
    if (i < N_NODES) {
        int off = g_tmp[i] + g_bsum[blockIdx.x];
        g_off[i + 1] = off;
        g_cur[i] = off - g_cnt[i];
        if (i == 0) g_off[0] = 0;
    }
}

__global__ void k_fill(const int* __restrict__ row, const int* __restrict__ col) {
    int e = blockIdx.x * blockDim.x + threadIdx.x;
    if (e < N_EDGES) {
        int c = col[e];
        int p = atomicAdd(&g_cur[c], 1);
        g_csr[p] = row[e];
    }
}

// ---------------- GEMM: g_hs = dinv * (opt BN+ReLU)(in) @ W ----------------
// M-tile 128, N=64. 256 threads; each computes 8m x 4n with n-packed f32x2 acc.
// a operand stored duplicated ({v,v}) in SMEM, node-major (no transpose, no
// bank conflicts); b operand read as aligned ulonglong2 straight from ws.
// Inner loop per k: 8 LDS.64 (broadcast) + 1 LDS.128 + 16 FFMA2.
#define KCH 32

template <int KDIM, bool BNRELU>
__global__ void __launch_bounds__(256) k_gemm(const float* __restrict__ in,
                                              const float* __restrict__ W) {
    extern __shared__ char smraw[];
    float (*ws)[68] = (float (*)[68])smraw;                       // [KDIM][68]
    u64 (*xsd)[KCH + 1] = (u64 (*)[KCH + 1])(smraw + KDIM * 68 * 4); // [128][33]

    int tid = threadIdx.x;
    int nb = blockIdx.x * 128;
    int mg = tid >> 4;   // 0..15 -> m base mg*8
    int ng = tid & 15;   // 0..15 -> n base ng*4

    // preload full W
    #pragma unroll
    for (int t = tid; t < KDIM * 64; t += 256) {
        int r = t >> 6, c = t & 63;
        ws[r][c] = W[(size_t)r * HID + c];
    }

    u64 acc[8][2];
    #pragma unroll
    for (int i = 0; i < 8; i++) { acc[i][0] = 0ull; acc[i][1] = 0ull; }

    for (int ko = 0; ko < KDIM; ko += KCH) {
        __syncthreads();
        // load x chunk: 128 nodes x KCH k, duplicated pairs, coalesced
        #pragma unroll
        for (int it = 0; it < 128 * KCH / 256; it++) {
            int idx = tid + it * 256;
            int r = idx >> 5, c = idx & (KCH - 1);
            int node = nb + r;
            float v = (node < N_NODES) ? in[(size_t)node * KDIM + ko + c] : 0.0f;
            if (BNRELU) v = fmaxf(v * g_bn[ko + c] + g_bn[64 + ko + c], 0.0f);
            xsd[r][c] = dup2(v);
        }
        __syncthreads();

        #pragma unroll 8
        for (int kk = 0; kk < KCH; kk++) {
            ulonglong2 bb = *(const ulonglong2*)&ws[ko + kk][ng * 4];
            #pragma unroll
            for (int i = 0; i < 8; i++) {
                u64 aa = xsd[mg * 8 + i][kk];
                acc[i][0] = ffma2(aa, bb.x, acc[i][0]);
                acc[i][1] = ffma2(aa, bb.y, acc[i][1]);
            }
        }
    }

    // epilogue: scale by dinv, store float4 per row
    #pragma unroll
    for (int i = 0; i < 8; i++) {
        int node = nb + mg * 8 + i;
        if (node < N_NODES) {
            float dv = g_dinv[node];
            uint2 q0 = *(uint2*)&acc[i][0];
            uint2 q1 = *(uint2*)&acc[i][1];
            float4 o;
            o.x = __uint_as_float(q0.x) * dv;
            o.y = __uint_as_float(q0.y) * dv;
            o.z = __uint_as_float(q1.x) * dv;
            o.w = __uint_as_float(q1.y) * dv;
            *(float4*)&g_hs[(size_t)node * HID + ng * 4] = o;
        }
    }
}

// ---------------- aggregation: agg[c] = dinv[c]*(sum_in hs[row] + hs[c]) + bias ----------------
__global__ void k_agg(const float* __restrict__ bias) {
    int w = (blockIdx.x * blockDim.x + threadIdx.x) >> 5;
    int lane = threadIdx.x & 31;
    if (w >= N_NODES) return;
    int s = g_off[w], e = g_off[w + 1];
    const u64* hs2 = (const u64*)g_hs;
    u64 acc0 = hs2[(size_t)w * 32 + lane];   // self-loop term
    u64 acc1 = 0ull;                          // bits 0 == {0.f, 0.f}
    int eb = s;
    for (; eb + 32 <= e; eb += 32) {
        int r = g_csr[eb + lane];
        #pragma unroll
        for (int j = 0; j < 32; j += 2) {
            int r0 = __shfl_sync(0xffffffffu, r, j);
            int r1 = __shfl_sync(0xffffffffu, r, j + 1);
            acc0 = fadd2(acc0, __ldg(&hs2[(size_t)r0 * 32 + lane]));
            acc1 = fadd2(acc1, __ldg(&hs2[(size_t)r1 * 32 + lane]));
        }
    }
    if (eb < e) {
        int n = e - eb;
        int r = (eb + lane < e) ? g_csr[eb + lane] : 0;
        for (int j = 0; j < n; j++) {
            int rr = __shfl_sync(0xffffffffu, r, j);
            u64 v = __ldg(&hs2[(size_t)rr * 32 + lane]);
            if (j & 1) acc1 = fadd2(acc1, v); else acc0 = fadd2(acc0, v);
        }
    }
    acc0 = fadd2(acc0, acc1);
    uint2 q = *(uint2*)&acc0;
    float dv = g_dinv[w];
    float2 b = ((const float2*)bias)[lane];
    float2 o;
    o.x = __uint_as_float(q.x) * dv + b.x;
    o.y = __uint_as_float(q.y) * dv + b.y;
    ((float2*)g_agg)[(size_t)w * 32 + lane] = o;
}

// ---------------- BN statistics (deterministic 2-stage) ----------------
__global__ void k_bnstat() {
    float s = 0.0f, q = 0.0f;
    const size_t total4 = (size_t)N_NODES * HID / 4;
    const float4* a4 = (const float4*)g_agg;
    for (size_t i = (size_t)blockIdx.x * 256 + threadIdx.x; i < total4; i += (size_t)NPART * 256) {
        float4 v = a4[i];
        s += v.x + v.y + v.z + v.w;
        q += v.x * v.x + v.y * v.y + v.z * v.z + v.w * v.w;
    }
    // NOTE: float4 groups 4 consecutive features; feature-wise sums must stay
    // feature-separated for BN. Revert to per-feature accumulation:
    (void)s; (void)q;
    // per-feature pass (strided so each thread keeps a fixed feature quartet)
    float s0 = 0, s1 = 0, s2 = 0, s3 = 0, q0 = 0, q1 = 0, q2 = 0, q3 = 0;
    int fquart = threadIdx.x & 15;            // 16 quartets cover 64 features
    int sub = (blockIdx.x * 16) + (threadIdx.x >> 4); // row-group stride NPART*16
    for (size_t n = sub; n < N_NODES; n += (size_t)NPART * 16) {
        float4 v = a4[n * 16 + fquart];
        s0 += v.x; s1 += v.y; s2 += v.z; s3 += v.w;
        q0 += v.x * v.x; q1 += v.y * v.y; q2 += v.z * v.z; q3 += v.w * v.w;
    }
    __shared__ float sh[256][8];
    sh[threadIdx.x][0] = s0; sh[threadIdx.x][1] = s1;
    sh[threadIdx.x][2] = s2; sh[threadIdx.x][3] = s3;
    sh[threadIdx.x][4] = q0; sh[threadIdx.x][5] = q1;
    sh[threadIdx.x][6] = q2; sh[threadIdx.x][7] = q3;
    __syncthreads();
    if (threadIdx.x < 64) {
        int fq = threadIdx.x >> 2, comp = threadIdx.x & 3;
        float ts = 0.0f, tq = 0.0f;
        for (int g = 0; g < 16; g++) {
            ts += sh[g * 16 + fq][comp];
            tq += sh[g * 16 + fq][4 + comp];
        }
        int f = fq * 4 + comp;
        g_part[blockIdx.x * 128 + f] = ts;
        g_part[blockIdx.x * 128 + 64 + f] = tq;
    }
}

__global__ void k_bnfinal(const float* __restrict__ gamma, const float* __restrict__ beta) {
    int f = threadIdx.x;
    float s = 0.0f, q = 0.0f;
    for (int b = 0; b < NPART; b++) {
        s += g_part[b * 128 + f];
        q += g_part[b * 128 + 64 + f];
    }
    const float invN = 1.0f / (float)N_NODES;
    float mean = s * invN;
    float var = q * invN - mean * mean;
    float rstd = rsqrtf(var + BN_EPS);
    float scale = rstd * gamma[f];
    g_bn[f] = scale;
    g_bn[64 + f] = beta[f] - mean * scale;
}

// ---------------- graph mean pool with fused BN3 ----------------
__device__ __forceinline__ int lower_bound_i(const int* a, int n, int v) {
    int lo = 0, hi = n;
    while (lo < hi) { int m = (lo + hi) >> 1; if (a[m] < v) lo = m + 1; else hi = m; }
    return lo;
}

__global__ void k_pool(const int* __restrict__ batch) {
    int g = blockIdx.x;
    __shared__ int ss, se;
    if (threadIdx.x == 0) {
        ss = lower_bound_i(batch, N_NODES, g);
        se = lower_bound_i(batch, N_NODES, g + 1);
    }
    __syncthreads();
    int f = threadIdx.x & 63, sub = threadIdx.x >> 6;
    float s = 0.0f;
    for (int n = ss + sub; n < se; n += 4) s += g_agg[(size_t)n * HID + f];
    __shared__ float sh[256];
    sh[threadIdx.x] = s;
    __syncthreads();
    if (threadIdx.x < 64) {
        float tot = sh[threadIdx.x] + sh[threadIdx.x + 64] + sh[threadIdx.x + 128] + sh[threadIdx.x + 192];
        int cnt = se - ss;
        float scale = g_bn[threadIdx.x], shift = g_bn[64 + threadIdx.x];
        float emb = (scale * tot + shift * (float)cnt) / fmaxf((float)cnt, 1.0f);
        g_emb[g * HID + threadIdx.x] = emb;
    }
}

// ---------------- centroid classifier ----------------
__global__ void k_cls(const float* __restrict__ cg, const float* __restrict__ cm,
                      const float* __restrict__ temp, float* __restrict__ out) {
    int g = blockIdx.x;
    __shared__ float e[64];
    __shared__ float dist[197];
    if (threadIdx.x < 64) e[threadIdx.x] = g_emb[g * HID + threadIdx.x];
    __syncthreads();
    for (int c = threadIdx.x; c < 197; c += 256) {
        const float* cp = (c < 5) ? (cg + (size_t)c * HID) : (cm + (size_t)(c - 5) * HID);
        float s = 0.0f;
        #pragma unroll
        for (int k = 0; k < 64; k++) { float d = e[k] - cp[k]; s += d * d; }
        dist[c] = s;
    }
    __syncthreads();
    float t = temp[0];
    if (threadIdx.x == 0) {
        float mg = dist[0];
        for (int c = 1; c < 5; c++) mg = fminf(mg, dist[c]);
        out[g * 65] = -mg / t;
    }
    if (threadIdx.x < 64) {
        int b = 5 + threadIdx.x * 3;
        float m = fminf(fminf(dist[b], dist[b + 1]), dist[b + 2]);
        out[g * 65 + 1 + threadIdx.x] = -m / t;
    }
}

// ---------------- host launcher ----------------
extern "C" void kernel_launch(void* const* d_in, const int* in_sizes, int n_in,
                              void* d_out, int out_size) {
    const float* x    = (const float*)d_in[0];
    const int*   ei   = (const int*)d_in[1];
    const int*   batch= (const int*)d_in[2];
    const float* W1 = (const float*)d_in[3];  const float* b1  = (const float*)d_in[4];
    const float* g1 = (const float*)d_in[5];  const float* be1 = (const float*)d_in[6];
    const float* W2 = (const float*)d_in[7];  const float* b2  = (const float*)d_in[8];
    const float* g2 = (const float*)d_in[9];  const float* be2 = (const float*)d_in[10];
    const float* W3 = (const float*)d_in[11]; const float* b3  = (const float*)d_in[12];
    const float* g3 = (const float*)d_in[13]; const float* be3 = (const float*)d_in[14];
    const float* cg = (const float*)d_in[15]; const float* cm  = (const float*)d_in[16];
    const float* temp = (const float*)d_in[17];
    float* out = (float*)d_out;

    const int* row = ei;
    const int* col = ei + N_EDGES;

    float* aggp = nullptr;
    cudaGetSymbolAddress((void**)&aggp, g_agg);
    int* cntp = nullptr;
    cudaGetSymbolAddress((void**)&cntp, g_cnt);

    const int SMEM1 = IN_DIM * 68 * 4 + 128 * (KCH + 1) * 8;  // 68608
    const int SMEM2 = HID * 68 * 4 + 128 * (KCH + 1) * 8;     // 51200
    cudaFuncSetAttribute(k_gemm<IN_DIM, false>, cudaFuncAttributeMaxDynamicSharedMemorySize, SMEM1);
    cudaFuncSetAttribute(k_gemm<HID, true>,     cudaFuncAttributeMaxDynamicSharedMemorySize, SMEM2);

    const int GEMM_BLOCKS = (N_NODES + 127) / 128; // 782
    const int EDGE_BLOCKS = (N_EDGES + 255) / 256; // 12500
    const int WARP_BLOCKS = (N_NODES + 7) / 8;     // 12500 (8 warps/block)

    // CSR build front half
    cudaMemsetAsync(cntp, 0, N_NODES * sizeof(int));
    k_count<<<EDGE_BLOCKS, 256>>>(col);
    k_dinv<<<SCAN_B, 1024>>>();

    // Layer 1 GEMM (only needs x, W1, dinv)
    k_gemm<IN_DIM, false><<<GEMM_BLOCKS, 256, SMEM1>>>(x, W1);

    // finish CSR build
    k_scan1<<<SCAN_B, 1024>>>();
    k_scan2<<<1, 128>>>();
    k_scan3<<<SCAN_B, 1024>>>();
    k_fill<<<EDGE_BLOCKS, 256>>>(row, col);

    // Layer 1 aggregate + BN
    k_agg<<<WARP_BLOCKS, 256>>>(b1);
    k_bnstat<<<NPART, 256>>>();
    k_bnfinal<<<1, 64>>>(g1, be1);

    // Layer 2 (BN1+ReLU fused into GEMM load)
    k_gemm<HID, true><<<GEMM_BLOCKS, 256, SMEM2>>>(aggp, W2);
    k_agg<<<WARP_BLOCKS, 256>>>(b2);
    k_bnstat<<<NPART, 256>>>();
    k_bnfinal<<<1, 64>>>(g2, be2);

    // Layer 3
    k_gemm<HID, true><<<GEMM_BLOCKS, 256, SMEM2>>>(aggp, W3);
    k_agg<<<WARP_BLOCKS, 256>>>(b3);
    k_bnstat<<<NPART, 256>>>();
    k_bnfinal<<<1, 64>>>(g3, be3);

    // Pool (BN3 fused) + classifier
    k_pool<<<N_GRAPHS, 256>>>(batch);
    k_cls<<<N_GRAPHS, 256>>>(cg, cm, temp, out);
}